// round 1
// baseline (speedup 1.0000x reference)
#include <cuda_runtime.h>
#include <math.h>
#include <stdint.h>

#define LVOX 4096
#define NBATCH 4
#define NB 8          // (branch, batch) pairs
#define MAXN 32       // max neighbors per voxel (analytic bound: <= 27)
#define CPB 4         // channels per phase-B block
#define TPB_B 512

// Scratch: static device globals (no allocation allowed)
__device__ int            g_ncnt[NB][LVOX];
__device__ unsigned short g_nbr[NB][MAXN][LVOX];   // t-major: coalesced over l
__device__ unsigned int   g_total[NB];
__device__ double         g_num[NB];

__global__ void k_zero() {
    int t = threadIdx.x;
    if (t < NB) { g_total[t] = 0u; g_num[t] = 0.0; }
}

// One thread per (nb, l): find masked k-neighbors of q-voxel l.
__global__ void k_phaseA(const float* __restrict__ cq, const float* __restrict__ ck) {
    int nb = blockIdx.y;
    int l  = blockIdx.x * blockDim.x + threadIdx.x;
    if (l >= LVOX) return;
    int br = nb >> 2;
    int n  = nb & 3;
    int qb = br ? (3 - n) : n;     // flipped q-batch for branch 1

    // q crop box (batch qb — flipped for branch 1)
    float q0 = cq[qb*6+0], q1 = cq[qb*6+1], q2 = cq[qb*6+2];
    float bq0 = (cq[qb*6+3] - q0) * (1.0f/16.0f);
    float bq1 = (cq[qb*6+4] - q1) * (1.0f/16.0f);
    float bq2 = (cq[qb*6+5] - q2) * (1.0f/16.0f);
    // k crop box (batch n)
    float k0 = ck[n*6+0], k1 = ck[n*6+1], k2 = ck[n*6+2];
    float bk0 = (ck[n*6+3] - k0) * (1.0f/16.0f);
    float bk1 = (ck[n*6+4] - k1) * (1.0f/16.0f);
    float bk2 = (ck[n*6+5] - k2) * (1.0f/16.0f);

    // max_diag uses UNFLIPPED diag_q[n] (closure in reference), diag_k[n]
    float a0 = (cq[n*6+3] - cq[n*6+0]) * (1.0f/16.0f);
    float a1 = (cq[n*6+4] - cq[n*6+1]) * (1.0f/16.0f);
    float a2 = (cq[n*6+5] - cq[n*6+2]) * (1.0f/16.0f);
    float diagq = sqrtf((a0*a0 + a1*a1) + a2*a2);
    float diagk = sqrtf((bk0*bk0 + bk1*bk1) + bk2*bk2);
    float md = fmaxf(diagq, diagk);
    float R  = 0.5f * md;

    int i  = l >> 8;
    int j  = (l >> 4) & 15;
    int kz = l & 15;
    float cx = fmaf((float)i  + 0.5f, bq0, q0);
    float cy = fmaf((float)j  + 0.5f, bq1, q1);
    float cz = fmaf((float)kz + 0.5f, bq2, q2);

    // Candidate box in k-grid coords (widened by floor/ceil for fp slack)
    int xlo = max(0,  (int)floorf((cx - R - k0) / bk0 - 0.5f));
    int xhi = min(15, (int)ceilf ((cx + R - k0) / bk0 - 0.5f));
    int ylo = max(0,  (int)floorf((cy - R - k1) / bk1 - 0.5f));
    int yhi = min(15, (int)ceilf ((cy + R - k1) / bk1 - 0.5f));
    int zlo = max(0,  (int)floorf((cz - R - k2) / bk2 - 0.5f));
    int zhi = min(15, (int)ceilf ((cz + R - k2) / bk2 - 0.5f));

    int cnt = 0;
    for (int jx = xlo; jx <= xhi; jx++) {
        float dx = cx - fmaf((float)jx + 0.5f, bk0, k0);
        for (int jy = ylo; jy <= yhi; jy++) {
            float dy = cy - fmaf((float)jy + 0.5f, bk1, k1);
            for (int jz = zlo; jz <= zhi; jz++) {
                float dz = cz - fmaf((float)jz + 0.5f, bk2, k2);
                float d2 = dx*dx + dy*dy + dz*dz;
                // Exact reference semantics: sqrt then divide then compare
                if (sqrtf(d2) / md < 0.5f) {
                    if (cnt < MAXN)
                        g_nbr[nb][cnt][l] = (unsigned short)(jx*256 + jy*16 + jz);
                    cnt++;
                }
            }
        }
    }
    if (cnt > MAXN) cnt = MAXN;   // analytic bound says never triggers
    g_ncnt[nb][l] = cnt;
    if (cnt) atomicAdd(&g_total[nb], (unsigned int)cnt);
}

// Block = (batch n, chunk of CPB channels). Handles BOTH branches for n.
__global__ void k_phaseB(const float* __restrict__ q, const float* __restrict__ k) {
    int n      = blockIdx.y;   // 0..3
    int cchunk = blockIdx.x;   // 0..79
    extern __shared__ float4 sm[];
    float4* qa = sm;             // q[n]     rows, c-innermost
    float4* qf = sm + LVOX;      // q[3-n]
    float4* kk = sm + 2 * LVOX;  // k[n]
    int tid = threadIdx.x;
    int qb2 = 3 - n;

    for (int cc = 0; cc < CPB; cc++) {
        int c = cchunk * CPB + cc;
        const float* qr  = q + ((size_t)n   * 320 + c) * (size_t)LVOX;
        const float* qr2 = q + ((size_t)qb2 * 320 + c) * (size_t)LVOX;
        const float* kr  = k + ((size_t)n   * 320 + c) * (size_t)LVOX;
        for (int i2 = tid; i2 < LVOX; i2 += blockDim.x) {
            ((float*)(qa + i2))[cc] = qr[i2];
            ((float*)(qf + i2))[cc] = qr2[i2];
            ((float*)(kk + i2))[cc] = kr[i2];
        }
    }
    __syncthreads();

    int nb0 = n, nb1 = 4 + n;
    float4 acc0 = {0.f,0.f,0.f,0.f};
    float4 acc1 = {0.f,0.f,0.f,0.f};
    for (int l = tid; l < LVOX; l += blockDim.x) {
        int c0 = g_ncnt[nb0][l];
        if (c0) {
            float4 s = {0.f,0.f,0.f,0.f};
            for (int t = 0; t < c0; t++) {
                int m = g_nbr[nb0][t][l];
                float4 kv = kk[m];
                s.x += kv.x; s.y += kv.y; s.z += kv.z; s.w += kv.w;
            }
            float4 qv = qa[l];
            acc0.x += qv.x * s.x; acc0.y += qv.y * s.y;
            acc0.z += qv.z * s.z; acc0.w += qv.w * s.w;
        }
        int c1 = g_ncnt[nb1][l];
        if (c1) {
            float4 s = {0.f,0.f,0.f,0.f};
            for (int t = 0; t < c1; t++) {
                int m = g_nbr[nb1][t][l];
                float4 kv = kk[m];
                s.x += kv.x; s.y += kv.y; s.z += kv.z; s.w += kv.w;
            }
            float4 qv = qf[l];
            acc1.x += qv.x * s.x; acc1.y += qv.y * s.y;
            acc1.z += qv.z * s.z; acc1.w += qv.w * s.w;
        }
    }

    double t0 = (double)acc0.x + (double)acc0.y + (double)acc0.z + (double)acc0.w;
    double t1 = (double)acc1.x + (double)acc1.y + (double)acc1.z + (double)acc1.w;
    for (int o = 16; o; o >>= 1) {
        t0 += __shfl_down_sync(0xFFFFFFFFu, t0, o);
        t1 += __shfl_down_sync(0xFFFFFFFFu, t1, o);
    }
    if ((tid & 31) == 0) {
        atomicAdd(&g_num[nb0], t0);
        atomicAdd(&g_num[nb1], t1);
    }
}

__global__ void k_final(float* out) {
    if (threadIdx.x == 0 && blockIdx.x == 0) {
        double s0 = 0.0, s1 = 0.0;
        for (int n = 0; n < NBATCH; n++) {
            s0 += g_num[n]     / ((double)g_total[n]     + 1e-6);
            s1 += g_num[4 + n] / ((double)g_total[4 + n] + 1e-6);
        }
        out[0] = (float)(-2.0 * (s0 / 4.0) - 2.0 * (s1 / 4.0));
    }
}

extern "C" void kernel_launch(void* const* d_in, const int* in_sizes, int n_in,
                              void* d_out, int out_size) {
    const float* q  = (const float*)d_in[0];
    const float* k  = (const float*)d_in[1];
    const float* cq = (const float*)d_in[2];
    const float* ck = (const float*)d_in[3];

    // 192KB dynamic smem opt-in (idempotent; legal during capture)
    cudaFuncSetAttribute(k_phaseB, cudaFuncAttributeMaxDynamicSharedMemorySize,
                         3 * LVOX * (int)sizeof(float4));

    k_zero<<<1, 32>>>();
    dim3 ga(LVOX / 256, NB);
    k_phaseA<<<ga, 256>>>(cq, ck);
    dim3 gb(320 / CPB, NBATCH);
    k_phaseB<<<gb, TPB_B, 3 * LVOX * (int)sizeof(float4)>>>(q, k);
    k_final<<<1, 32>>>((float*)d_out);
}